// round 14
// baseline (speedup 1.0000x reference)
#include <cuda_runtime.h>
#include <cuda_bf16.h>
#include <cstdint>

#define N_NODES  200000
#define N_EDGES  800000
#define IN_CH    128
#define OUT_CH   64
#define MAX_DEG  4
#define N_GRAPHS 8192

// ---------------- scratch ----------------
__device__ int    fpnn_stride;                        // 1 = int32 inputs, 2 = int64
__device__ int    fpnn_deg[N_NODES];
__device__ int    fpnn_off[N_NODES];
__device__ int    fpnn_fill[N_NODES];
__device__ int    fpnn_csr[N_EDGES];
__device__ int    fpnn_cnt[8];                        // [0..4] buckets, [5] cursor
__device__ int    fpnn_lists[(MAX_DEG + 1) * N_NODES];
__device__ uint4  fpnn_wsp4[20480];                   // fragment-ordered split weights
__device__ float2 fpnn_pre2[(size_t)N_NODES * (OUT_CH / 2)];  // 51.2 MB

// ---------------- degree count (+ block-local dtype detect) ----------------
__global__ void fpnn_deg_kernel(const int* __restrict__ ei32) {
    __shared__ int s_st;
    if (threadIdx.x == 0) {
        int nz = 0;
#pragma unroll
        for (int j = 0; j < 8; j++) nz |= ei32[2 * j + 1];
        int st = (nz == 0) ? 2 : 1;
        s_st = st;
        if (blockIdx.x == 0) fpnn_stride = st;
    }
    __syncthreads();
    int e = blockIdx.x * blockDim.x + threadIdx.x;
    if (e >= N_EDGES) return;
    int dst = ei32[(size_t)s_st * (N_EDGES + e)];
    atomicAdd(&fpnn_deg[dst], 1);
}

// ---------------- split-bf16 helpers ----------------
__device__ __forceinline__ unsigned fpnn_pack(float f0, float f1) {
    unsigned u0 = (unsigned)__bfloat16_as_ushort(__float2bfloat16_rn(f0));
    unsigned u1 = (unsigned)__bfloat16_as_ushort(__float2bfloat16_rn(f1));
    return (u1 << 16) | u0;
}
__device__ __forceinline__ uint2 fpnn_split2(float f0, float f1) {
    float h0 = __bfloat162float(__float2bfloat16_rn(f0));
    float h1 = __bfloat162float(__float2bfloat16_rn(f1));
    uint2 p;
    p.x = fpnn_pack(h0, h1);
    p.y = fpnn_pack(f0 - h0, f1 - h1);
    return p;
}
// uint4-cell smem index with XOR bank swizzle; 16 cells per row
__device__ __forceinline__ int fpnn_swx(int row, int c) {
    return row * 16 + (c ^ (row & 7));
}

// ---------------- offset alloc + bucketize + weight pre-split -------------------
// Cell c of a chunk holds the split of chunk float4 position p = (c>>2) + 4*(c&3):
// khalf A = floats (4p, 4p+1), khalf B = floats (4p+2, 4p+3). Matches the A-side
// gather mapping (thread kt, q -> position kt+4q -> cell kt*4+q).
__global__ void fpnn_alloc_kernel(const float* __restrict__ Wlin,
                                  const float* __restrict__ Wroot) {
    int n = blockIdx.x * blockDim.x + threadIdx.x;
    if (n < N_NODES) {
        int deg = fpnn_deg[n];
        fpnn_off[n] = atomicAdd(&fpnn_cnt[5], deg);
        fpnn_fill[n] = 0;
        int d = min(deg, MAX_DEG);
        int pos = atomicAdd(&fpnn_cnt[d], 1);
        fpnn_lists[d * N_NODES + pos] = n;
    }
    if (n < 20480) {
        int cell = n & 15;
        int ch = (n >> 4) & 63;
        int dc = n >> 10;               // d*4 + chunk, 0..19
        int d = dc >> 2, chunk = dc & 3;
        const float* w = (chunk < 2)
            ? Wlin  + (size_t)d * IN_CH * OUT_CH + (size_t)(chunk * 64) * OUT_CH
            : Wroot + (size_t)d * IN_CH * OUT_CH + (size_t)((chunk - 2) * 64) * OUT_CH;
        int p = (cell >> 2) + 4 * (cell & 3);   // float4 position in chunk
        int k0 = p * 4;
        float f0 = w[(size_t)k0 * OUT_CH + ch];
        float f1 = w[(size_t)(k0 + 1) * OUT_CH + ch];
        float f2 = w[(size_t)(k0 + 2) * OUT_CH + ch];
        float f3 = w[(size_t)(k0 + 3) * OUT_CH + ch];
        uint2 p1 = fpnn_split2(f0, f1);
        uint2 p2 = fpnn_split2(f2, f3);
        uint4 q; q.x = p1.x; q.y = p1.y; q.z = p2.x; q.w = p2.y;
        fpnn_wsp4[n] = q;
    }
}

// ---------------- fill CSR ----------------
__global__ void fpnn_fill_kernel(const int* __restrict__ ei32) {
    int e = blockIdx.x * blockDim.x + threadIdx.x;
    if (e >= N_EDGES) return;
    int st = fpnn_stride;
    int src = ei32[(size_t)st * e];
    int dst = ei32[(size_t)st * (N_EDGES + e)];
    int pos = fpnn_off[dst] + atomicAdd(&fpnn_fill[dst], 1);
    fpnn_csr[pos] = src;
}

#define FPNN_MMA(d, a0, a1, a2, a3, b0, b1)                                   \
    asm volatile(                                                             \
        "mma.sync.aligned.m16n8k16.row.col.f32.bf16.bf16.f32 "                \
        "{%0,%1,%2,%3},{%4,%5,%6,%7},{%8,%9},{%0,%1,%2,%3};"                  \
        : "+f"(d[0]), "+f"(d[1]), "+f"(d[2]), "+f"(d[3])                      \
        : "r"(a0), "r"(a1), "r"(a2), "r"(a3), "r"(b0), "r"(b1))

// ---------------- fused gather + split-bf16 tensor GEMM ----------------
// Gather is lane-consecutive: thread (nl, kt) reads float4 positions kt + 4q
// (lanes kt=0..3 cover 64B dense per node per instruction).
#define M_TILE 64
#define MAX_TILES ((N_NODES + M_TILE - 1) / M_TILE + MAX_DEG + 1)   // 3130
__global__ void __launch_bounds__(256, 3)
fpnn_mma_kernel(const float4* __restrict__ x4) {
    __shared__ uint4 A_s[64 * 16];   // [node][cell], 16 KB
    __shared__ uint4 B_s[64 * 16];   // [ch][cell], 16 KB

    int tg = blockIdx.x;
    int d = 0, tile = 0, count = 0;
    {
        int base = 0;
        bool found = false;
#pragma unroll
        for (int b = 0; b <= MAX_DEG; b++) {
            int c = fpnn_cnt[b];
            int t = (c + M_TILE - 1) >> 6;
            if (!found && tg < base + t) {
                d = b; tile = tg - base; count = c; found = true;
            }
            base += t;
        }
        if (!found) return;
    }

    const int* list = fpnn_lists + d * N_NODES;

    int tid = threadIdx.x;
    int nl = tid >> 2, kt = tid & 3;          // A loader: node slot x lane-quarter
    int bn = tid & 63, bkg = tid >> 6;        // B loader: channel x cell-quarter
    int wid = tid >> 5, lane = tid & 31;
    int m0 = (wid & 3) * 16, n0 = (wid >> 2) * 32;
    int g = lane >> 2, t = lane & 3;

    float acc[4][4];
#pragma unroll
    for (int i = 0; i < 4; i++)
#pragma unroll
        for (int j = 0; j < 4; j++) acc[i][j] = 0.f;

#pragma unroll
    for (int chunk = 0; chunk < 4; chunk++) {
        // ---- A chunk: gathered agg (chunks 0,1) or own x (chunks 2,3) ----
        float4 v4[4];
#pragma unroll
        for (int q = 0; q < 4; q++) v4[q] = make_float4(0.f, 0.f, 0.f, 0.f);
        int nidx = tile * M_TILE + nl;
        if (nidx < count) {
            int n = list[nidx];
            if (chunk < 2) {
                int deg = fpnn_deg[n];
                int off = fpnn_off[n];
                for (int i = 0; i < deg; i++) {
                    int src = fpnn_csr[off + i];
                    const float4* r = x4 + (size_t)src * 32 + chunk * 16 + kt;
#pragma unroll
                    for (int q = 0; q < 4; q++) {
                        float4 a = r[4 * q];          // position kt + 4q
                        v4[q].x += a.x; v4[q].y += a.y;
                        v4[q].z += a.z; v4[q].w += a.w;
                    }
                }
            } else {
                const float4* r = x4 + (size_t)n * 32 + (chunk - 2) * 16 + kt;
#pragma unroll
                for (int q = 0; q < 4; q++) v4[q] = r[4 * q];
            }
        }
        // 4 STS.128: cell kt*4+q = split of float4 position kt+4q
#pragma unroll
        for (int q = 0; q < 4; q++) {
            uint2 p1 = fpnn_split2(v4[q].x, v4[q].y);
            uint2 p2 = fpnn_split2(v4[q].z, v4[q].w);
            uint4 qq; qq.x = p1.x; qq.y = p1.y; qq.z = p2.x; qq.w = p2.y;
            A_s[fpnn_swx(nl, kt * 4 + q)] = qq;
        }

        // ---- B chunk: fragment-ordered pre-split weights ----
        {
            const uint4* wsrc = fpnn_wsp4 + ((d * 4 + chunk) * 64 + bn) * 16 + bkg * 4;
#pragma unroll
            for (int u = 0; u < 4; u++)
                B_s[fpnn_swx(bn, bkg * 4 + u)] = wsrc[u];
        }
        __syncthreads();

        // ---- mma: 4 k-steps of 16 ----
#pragma unroll
        for (int ks = 0; ks < 4; ks++) {
            int c = ks * 4 + t;
            uint4 qa0 = A_s[fpnn_swx(m0 + g,     c)];
            uint4 qa1 = A_s[fpnn_swx(m0 + g + 8, c)];
#pragma unroll
            for (int ns = 0; ns < 4; ns++) {
                uint4 qb = B_s[fpnn_swx(n0 + ns * 8 + g, c)];
                FPNN_MMA(acc[ns], qa0.x, qa1.x, qa0.z, qa1.z, qb.x, qb.z); // hi*hi
                FPNN_MMA(acc[ns], qa0.x, qa1.x, qa0.z, qa1.z, qb.y, qb.w); // hi*lo
                FPNN_MMA(acc[ns], qa0.y, qa1.y, qa0.w, qa1.w, qb.x, qb.z); // lo*hi
            }
        }
        __syncthreads();
    }

    // ---- store ----
    int r0 = tile * M_TILE + m0 + g;
    int r1 = r0 + 8;
#pragma unroll
    for (int ns = 0; ns < 4; ns++) {
        int ncol_half = (n0 >> 1) + ns * 4 + t;
        if (r0 < count) {
            int n = list[r0];
            fpnn_pre2[(size_t)n * 32 + ncol_half] = make_float2(acc[ns][0], acc[ns][1]);
        }
        if (r1 < count) {
            int n = list[r1];
            fpnn_pre2[(size_t)n * 32 + ncol_half] = make_float2(acc[ns][2], acc[ns][3]);
        }
    }
}

// ---------------- fused relu + softmax + pool (warp per 8 sorted nodes) ---------
#define NODES_PER_WARP 8
__global__ void fpnn_spool_kernel(const int* __restrict__ b32,
                                  float* __restrict__ out) {
    int warp = (blockIdx.x * blockDim.x + threadIdx.x) >> 5;
    int lane = threadIdx.x & 31;
    int n0 = warp * NODES_PER_WARP;
    if (n0 >= N_NODES) return;
    int st = fpnn_stride;

    float2 acc = make_float2(0.f, 0.f);
    int gcur = b32[(size_t)st * n0];

#pragma unroll
    for (int i = 0; i < NODES_PER_WARP; i++) {
        int n = n0 + i;
        int g = b32[(size_t)st * n];
        if (g != gcur) {
            atomicAdd(out + (size_t)gcur * OUT_CH + 2 * lane,     acc.x);
            atomicAdd(out + (size_t)gcur * OUT_CH + 2 * lane + 1, acc.y);
            acc = make_float2(0.f, 0.f);
            gcur = g;
        }
        float2 v = fpnn_pre2[(size_t)n * 32 + lane];
        v.x = fmaxf(v.x, 0.f);
        v.y = fmaxf(v.y, 0.f);
        float m = fmaxf(v.x, v.y);
#pragma unroll
        for (int s = 16; s; s >>= 1) m = fmaxf(m, __shfl_xor_sync(0xffffffffu, m, s));
        float ex = __expf(v.x - m), ey = __expf(v.y - m);
        float s = ex + ey;
#pragma unroll
        for (int ss = 16; ss; ss >>= 1) s += __shfl_xor_sync(0xffffffffu, s, ss);
        float inv = 1.0f / s;
        acc.x += ex * inv;
        acc.y += ey * inv;
    }
    atomicAdd(out + (size_t)gcur * OUT_CH + 2 * lane,     acc.x);
    atomicAdd(out + (size_t)gcur * OUT_CH + 2 * lane + 1, acc.y);
}

// ---------------- launch ----------------
extern "C" void kernel_launch(void* const* d_in, const int* in_sizes, int n_in,
                              void* d_out, int out_size) {
    const float* x = 0; const int* ei32 = 0; const int* b32 = 0;
    const float* Wlin = 0; const float* Wroot = 0;
    for (int i = 0; i < n_in; i++) {
        int s = in_sizes[i];
        if      (s == N_NODES * IN_CH)        x    = (const float*)d_in[i];
        else if (s == 2 * N_EDGES)            ei32 = (const int*)d_in[i];
        else if (s == N_NODES)                b32  = (const int*)d_in[i];
        else if (s == (MAX_DEG + 1) * IN_CH * OUT_CH) {
            if (!Wlin) Wlin = (const float*)d_in[i];
            else       Wroot = (const float*)d_in[i];
        }
    }
    if (!x)     x     = (const float*)d_in[0];
    if (!ei32)  ei32  = (const int*)d_in[1];
    if (!b32)   b32   = (const int*)d_in[2];
    if (!Wlin)  Wlin  = (const float*)d_in[3];
    if (!Wroot) Wroot = (const float*)d_in[4];
    float* out = (float*)d_out;

    void* p_deg = 0; void* p_cnt = 0;
    cudaGetSymbolAddress(&p_deg, fpnn_deg);
    cudaGetSymbolAddress(&p_cnt, fpnn_cnt);
    cudaMemsetAsync(p_deg, 0, N_NODES * sizeof(int));
    cudaMemsetAsync(p_cnt, 0, 8 * sizeof(int));
    cudaMemsetAsync(d_out, 0, (size_t)out_size * sizeof(float));

    fpnn_deg_kernel<<<(N_EDGES + 255) / 256, 256>>>(ei32);
    fpnn_alloc_kernel<<<(N_NODES + 255) / 256, 256>>>(Wlin, Wroot);
    fpnn_fill_kernel<<<(N_EDGES + 255) / 256, 256>>>(ei32);
    fpnn_mma_kernel<<<MAX_TILES, 256>>>((const float4*)x);
    fpnn_spool_kernel<<<(N_NODES / NODES_PER_WARP * 32 + 255) / 256, 256>>>(b32, out);
}

// round 15
// speedup vs baseline: 1.2716x; 1.2716x over previous
#include <cuda_runtime.h>
#include <cuda_bf16.h>
#include <cstdint>

#define N_NODES  200000
#define N_EDGES  800000
#define IN_CH    128
#define OUT_CH   64
#define MAX_DEG  4
#define N_GRAPHS 8192

// ---------------- scratch ----------------
__device__ int    fpnn_stride;                        // 1 = int32 inputs, 2 = int64
__device__ int    fpnn_deg[N_NODES];
__device__ int    fpnn_off[N_NODES];
__device__ int    fpnn_fill[N_NODES];
__device__ int    fpnn_csr[N_EDGES];
__device__ int    fpnn_cnt[8];                        // [0..4] buckets, [5] cursor
__device__ int    fpnn_lists[(MAX_DEG + 1) * N_NODES];
// B fragments, warp-contiguous: [((d*2+pass)*8 + ks)*256 + n*4 + t]
__device__ uint4  fpnn_wspB[20480];                   // 320 KB
__device__ float2 fpnn_pre2[(size_t)N_NODES * (OUT_CH / 2)];  // 51.2 MB

// ---------------- degree count (+ block-local dtype detect) ----------------
__global__ void fpnn_deg_kernel(const int* __restrict__ ei32) {
    __shared__ int s_st;
    if (threadIdx.x == 0) {
        int nz = 0;
#pragma unroll
        for (int j = 0; j < 8; j++) nz |= ei32[2 * j + 1];
        int st = (nz == 0) ? 2 : 1;
        s_st = st;
        if (blockIdx.x == 0) fpnn_stride = st;
    }
    __syncthreads();
    int e = blockIdx.x * blockDim.x + threadIdx.x;
    if (e >= N_EDGES) return;
    int dst = ei32[(size_t)s_st * (N_EDGES + e)];
    atomicAdd(&fpnn_deg[dst], 1);
}

// ---------------- split-bf16 helpers ----------------
__device__ __forceinline__ unsigned fpnn_pack(float f0, float f1) {
    unsigned u0 = (unsigned)__bfloat16_as_ushort(__float2bfloat16_rn(f0));
    unsigned u1 = (unsigned)__bfloat16_as_ushort(__float2bfloat16_rn(f1));
    return (u1 << 16) | u0;
}
__device__ __forceinline__ uint2 fpnn_split2(float f0, float f1) {
    float h0 = __bfloat162float(__float2bfloat16_rn(f0));
    float h1 = __bfloat162float(__float2bfloat16_rn(f1));
    uint2 p;
    p.x = fpnn_pack(h0, h1);
    p.y = fpnn_pack(f0 - h0, f1 - h1);
    return p;
}
__device__ __forceinline__ uint4 fpnn_split4(float4 v) {
    uint2 p1 = fpnn_split2(v.x, v.y);
    uint2 p2 = fpnn_split2(v.z, v.w);
    uint4 q; q.x = p1.x; q.y = p1.y; q.z = p2.x; q.w = p2.y;
    return q;
}

// ---------------- alloc + bucketize + weight pre-split (B-fragment order) -------
// Cell c (0..31) of a pass covers float4 position p = (c>>3) + 4*(c&7) of the
// 128-float half: khalf 2p = floats (4p,4p+1) in .x/.y (hi/lo), khalf 2p+1 in .z/.w.
// B index: ((d*2+pass)*8 + ks)*256 + n*4 + t, with c = ks*4 + t  -> per mma
// instruction the warp (8 g x 4 t) reads 32 consecutive uint4 (512B).
__global__ void fpnn_alloc_kernel(const float* __restrict__ Wlin,
                                  const float* __restrict__ Wroot) {
    int n = blockIdx.x * blockDim.x + threadIdx.x;
    if (n < N_NODES) {
        int deg = fpnn_deg[n];
        fpnn_off[n] = atomicAdd(&fpnn_cnt[5], deg);
        fpnn_fill[n] = 0;
        int d = min(deg, MAX_DEG);
        int pos = atomicAdd(&fpnn_cnt[d], 1);
        fpnn_lists[d * N_NODES + pos] = n;
    }
    if (n < 20480) {
        int t  = n & 3;
        int ch = (n >> 2) & 63;
        int ks = (n >> 8) & 7;
        int dp = n >> 11;                 // 0..9
        int d = dp >> 1, pass = dp & 1;
        int c = ks * 4 + t;
        int p = (c >> 3) + 4 * (c & 7);   // float4 position 0..31
        const float* w = (pass == 0 ? Wlin : Wroot) + (size_t)d * IN_CH * OUT_CH;
        int k0 = 4 * p;
        float4 f;
        f.x = w[(size_t)k0 * OUT_CH + ch];
        f.y = w[(size_t)(k0 + 1) * OUT_CH + ch];
        f.z = w[(size_t)(k0 + 2) * OUT_CH + ch];
        f.w = w[(size_t)(k0 + 3) * OUT_CH + ch];
        fpnn_wspB[n] = fpnn_split4(f);
    }
}

// ---------------- fill CSR ----------------
__global__ void fpnn_fill_kernel(const int* __restrict__ ei32) {
    int e = blockIdx.x * blockDim.x + threadIdx.x;
    if (e >= N_EDGES) return;
    int st = fpnn_stride;
    int src = ei32[(size_t)st * e];
    int dst = ei32[(size_t)st * (N_EDGES + e)];
    int pos = fpnn_off[dst] + atomicAdd(&fpnn_fill[dst], 1);
    fpnn_csr[pos] = src;
}

#define FPNN_MMA(d, a0, a1, a2, a3, b0, b1)                                   \
    asm volatile(                                                             \
        "mma.sync.aligned.m16n8k16.row.col.f32.bf16.bf16.f32 "                \
        "{%0,%1,%2,%3},{%4,%5,%6,%7},{%8,%9},{%0,%1,%2,%3};"                  \
        : "+f"(d[0]), "+f"(d[1]), "+f"(d[2]), "+f"(d[3])                      \
        : "r"(a0), "r"(a1), "r"(a2), "r"(a3), "r"(b0), "r"(b1))

// ---------------- fused gather + split-bf16 tensor GEMM ----------------
// Two passes over K=128 each: pass 0 = gathered agg @ Wlin (ONE CSR walk for the
// full row), pass 1 = own x @ Wroot. A through 32KB smem; B direct LDG (L1-hit).
#define M_TILE 64
#define MAX_TILES ((N_NODES + M_TILE - 1) / M_TILE + MAX_DEG + 1)   // 3130
__global__ void __launch_bounds__(256, 3)
fpnn_mma_kernel(const float4* __restrict__ x4) {
    __shared__ uint4 A_s[64 * 32];   // [node][cell 0..31], 32 KB

    int tg = blockIdx.x;
    int d = 0, tile = 0, count = 0;
    {
        int base = 0;
        bool found = false;
#pragma unroll
        for (int b = 0; b <= MAX_DEG; b++) {
            int c = fpnn_cnt[b];
            int t = (c + M_TILE - 1) >> 6;
            if (!found && tg < base + t) {
                d = b; tile = tg - base; count = c; found = true;
            }
            base += t;
        }
        if (!found) return;
    }

    const int* list = fpnn_lists + d * N_NODES;

    int tid = threadIdx.x;
    int nl = tid >> 2, kt = tid & 3;          // A loader: node slot x lane-quarter
    int wid = tid >> 5, lane = tid & 31;
    int m0 = (wid & 3) * 16, n0 = (wid >> 2) * 32;
    int g = lane >> 2, t = lane & 3;

    float acc[4][4];
#pragma unroll
    for (int i = 0; i < 4; i++)
#pragma unroll
        for (int j = 0; j < 4; j++) acc[i][j] = 0.f;

    int nidx = tile * M_TILE + nl;
    int nnode = (nidx < count) ? list[nidx] : -1;

#pragma unroll
    for (int pass = 0; pass < 2; pass++) {
        // ---- A: full 128-float row (8 float4s, positions kt + 4q) ----
        float4 v4[8];
#pragma unroll
        for (int q = 0; q < 8; q++) v4[q] = make_float4(0.f, 0.f, 0.f, 0.f);
        if (nnode >= 0) {
            if (pass == 0) {
                int deg = fpnn_deg[nnode];
                int off = fpnn_off[nnode];
                for (int i = 0; i < deg; i++) {
                    int src = fpnn_csr[off + i];
                    const float4* r = x4 + (size_t)src * 32 + kt;
#pragma unroll
                    for (int q = 0; q < 8; q++) {
                        float4 a = r[4 * q];
                        v4[q].x += a.x; v4[q].y += a.y;
                        v4[q].z += a.z; v4[q].w += a.w;
                    }
                }
            } else {
                const float4* r = x4 + (size_t)nnode * 32 + kt;
#pragma unroll
                for (int q = 0; q < 8; q++) v4[q] = r[4 * q];
            }
        }
        // cell kt*8+q holds position kt+4q; bijection matches B's c->p map.
#pragma unroll
        for (int q = 0; q < 8; q++)
            A_s[nl * 32 + (((kt * 8 + q)) ^ (nl & 7))] = fpnn_split4(v4[q]);
        __syncthreads();

        // ---- mma: 8 k-steps of 16; B straight from global (L1-hit, 512B/warp) --
        const uint4* wb = fpnn_wspB + (size_t)((d * 2 + pass) * 8) * 256;
#pragma unroll
        for (int ks = 0; ks < 8; ks++) {
            int c = ks * 4 + t;
            uint4 qa0 = A_s[(m0 + g) * 32 + (c ^ g)];
            uint4 qa1 = A_s[(m0 + g + 8) * 32 + (c ^ g)];
            const uint4* wrow = wb + ks * 256;
#pragma unroll
            for (int ns = 0; ns < 4; ns++) {
                uint4 qb = wrow[(n0 + ns * 8 + g) * 4 + t];
                FPNN_MMA(acc[ns], qa0.x, qa1.x, qa0.z, qa1.z, qb.x, qb.z); // hi*hi
                FPNN_MMA(acc[ns], qa0.x, qa1.x, qa0.z, qa1.z, qb.y, qb.w); // hi*lo
                FPNN_MMA(acc[ns], qa0.y, qa1.y, qa0.w, qa1.w, qb.x, qb.z); // lo*hi
            }
        }
        if (pass == 0) __syncthreads();   // protect A_s before pass-1 overwrite
    }

    // ---- store ----
    int r0 = tile * M_TILE + m0 + g;
    int r1 = r0 + 8;
#pragma unroll
    for (int ns = 0; ns < 4; ns++) {
        int ncol_half = (n0 >> 1) + ns * 4 + t;
        if (r0 < count) {
            int n = list[r0];
            fpnn_pre2[(size_t)n * 32 + ncol_half] = make_float2(acc[ns][0], acc[ns][1]);
        }
        if (r1 < count) {
            int n = list[r1];
            fpnn_pre2[(size_t)n * 32 + ncol_half] = make_float2(acc[ns][2], acc[ns][3]);
        }
    }
}

// ---------------- fused relu + softmax + pool (warp per 8 sorted nodes) ---------
#define NODES_PER_WARP 8
__global__ void fpnn_spool_kernel(const int* __restrict__ b32,
                                  float* __restrict__ out) {
    int warp = (blockIdx.x * blockDim.x + threadIdx.x) >> 5;
    int lane = threadIdx.x & 31;
    int n0 = warp * NODES_PER_WARP;
    if (n0 >= N_NODES) return;
    int st = fpnn_stride;

    float2 acc = make_float2(0.f, 0.f);
    int gcur = b32[(size_t)st * n0];

#pragma unroll
    for (int i = 0; i < NODES_PER_WARP; i++) {
        int n = n0 + i;
        int g = b32[(size_t)st * n];
        if (g != gcur) {
            atomicAdd(out + (size_t)gcur * OUT_CH + 2 * lane,     acc.x);
            atomicAdd(out + (size_t)gcur * OUT_CH + 2 * lane + 1, acc.y);
            acc = make_float2(0.f, 0.f);
            gcur = g;
        }
        float2 v = fpnn_pre2[(size_t)n * 32 + lane];
        v.x = fmaxf(v.x, 0.f);
        v.y = fmaxf(v.y, 0.f);
        float m = fmaxf(v.x, v.y);
#pragma unroll
        for (int s = 16; s; s >>= 1) m = fmaxf(m, __shfl_xor_sync(0xffffffffu, m, s));
        float ex = __expf(v.x - m), ey = __expf(v.y - m);
        float s = ex + ey;
#pragma unroll
        for (int ss = 16; ss; ss >>= 1) s += __shfl_xor_sync(0xffffffffu, s, ss);
        float inv = 1.0f / s;
        acc.x += ex * inv;
        acc.y += ey * inv;
    }
    atomicAdd(out + (size_t)gcur * OUT_CH + 2 * lane,     acc.x);
    atomicAdd(out + (size_t)gcur * OUT_CH + 2 * lane + 1, acc.y);
}

// ---------------- launch ----------------
extern "C" void kernel_launch(void* const* d_in, const int* in_sizes, int n_in,
                              void* d_out, int out_size) {
    const float* x = 0; const int* ei32 = 0; const int* b32 = 0;
    const float* Wlin = 0; const float* Wroot = 0;
    for (int i = 0; i < n_in; i++) {
        int s = in_sizes[i];
        if      (s == N_NODES * IN_CH)        x    = (const float*)d_in[i];
        else if (s == 2 * N_EDGES)            ei32 = (const int*)d_in[i];
        else if (s == N_NODES)                b32  = (const int*)d_in[i];
        else if (s == (MAX_DEG + 1) * IN_CH * OUT_CH) {
            if (!Wlin) Wlin = (const float*)d_in[i];
            else       Wroot = (const float*)d_in[i];
        }
    }
    if (!x)     x     = (const float*)d_in[0];
    if (!ei32)  ei32  = (const int*)d_in[1];
    if (!b32)   b32   = (const int*)d_in[2];
    if (!Wlin)  Wlin  = (const float*)d_in[3];
    if (!Wroot) Wroot = (const float*)d_in[4];
    float* out = (float*)d_out;

    void* p_deg = 0; void* p_cnt = 0;
    cudaGetSymbolAddress(&p_deg, fpnn_deg);
    cudaGetSymbolAddress(&p_cnt, fpnn_cnt);
    cudaMemsetAsync(p_deg, 0, N_NODES * sizeof(int));
    cudaMemsetAsync(p_cnt, 0, 8 * sizeof(int));
    cudaMemsetAsync(d_out, 0, (size_t)out_size * sizeof(float));

    fpnn_deg_kernel<<<(N_EDGES + 255) / 256, 256>>>(ei32);
    fpnn_alloc_kernel<<<(N_NODES + 255) / 256, 256>>>(Wlin, Wroot);
    fpnn_fill_kernel<<<(N_EDGES + 255) / 256, 256>>>(ei32);
    fpnn_mma_kernel<<<MAX_TILES, 256>>>((const float4*)x);
    fpnn_spool_kernel<<<(N_NODES / NODES_PER_WARP * 32 + 255) / 256, 256>>>(b32, out);
}

// round 16
// speedup vs baseline: 1.2811x; 1.0074x over previous
#include <cuda_runtime.h>
#include <cuda_bf16.h>
#include <cstdint>

#define N_NODES  200000
#define N_EDGES  800000
#define IN_CH    128
#define OUT_CH   64
#define MAX_DEG  4
#define N_GRAPHS 8192

// ---------------- scratch ----------------
__device__ int    fpnn_stride;                        // 1 = int32 inputs, 2 = int64
__device__ int    fpnn_deg[N_NODES];
__device__ int    fpnn_off[N_NODES];
__device__ int    fpnn_fill[N_NODES];
__device__ int    fpnn_csr[N_EDGES];
__device__ int    fpnn_cnt[8];                        // [0..4] buckets, [5] cursor
__device__ int    fpnn_lists[(MAX_DEG + 1) * N_NODES];
// B fragments, warp-contiguous: [((d*2+pass)*8 + ks)*256 + n*4 + t]
__device__ uint4  fpnn_wspB[20480];                   // 320 KB
__device__ float2 fpnn_pre2[(size_t)N_NODES * (OUT_CH / 2)];  // 51.2 MB

// ---------------- degree count (+ block-local dtype detect) ----------------
__global__ void fpnn_deg_kernel(const int* __restrict__ ei32) {
    __shared__ int s_st;
    if (threadIdx.x == 0) {
        int nz = 0;
#pragma unroll
        for (int j = 0; j < 8; j++) nz |= ei32[2 * j + 1];
        int st = (nz == 0) ? 2 : 1;
        s_st = st;
        if (blockIdx.x == 0) fpnn_stride = st;
    }
    __syncthreads();
    int e = blockIdx.x * blockDim.x + threadIdx.x;
    if (e >= N_EDGES) return;
    int dst = ei32[(size_t)s_st * (N_EDGES + e)];
    atomicAdd(&fpnn_deg[dst], 1);
}

// ---------------- packed helpers (sm_103a) ----------------
// dual convert+pack: f0 -> low bf16, f1 -> high bf16, one instruction
__device__ __forceinline__ unsigned fpnn_cvtpack(float f0, float f1) {
    unsigned r;
    asm("cvt.rn.bf16x2.f32 %0, %1, %2;" : "=r"(r) : "f"(f1), "f"(f0));
    return r;
}
__device__ __forceinline__ uint4 fpnn_split4(float4 v) {
    uint4 q;
    q.x = fpnn_cvtpack(v.x, v.y);
    q.z = fpnn_cvtpack(v.z, v.w);
    float h0 = __uint_as_float(q.x << 16);
    float h1 = __uint_as_float(q.x & 0xffff0000u);
    float h2 = __uint_as_float(q.z << 16);
    float h3 = __uint_as_float(q.z & 0xffff0000u);
    q.y = fpnn_cvtpack(v.x - h0, v.y - h1);
    q.w = fpnn_cvtpack(v.z - h2, v.w - h3);
    return q;
}
#define FPNN_ADD2(acc, val) \
    asm("add.rn.f32x2 %0, %0, %1;" : "+l"(acc) : "l"(val))
#define FPNN_PACK64(dst, lo, hi) \
    asm("mov.b64 %0, {%1, %2};" : "=l"(dst) : "f"(lo), "f"(hi))
#define FPNN_UNPACK64(lo, hi, src) \
    asm("mov.b64 {%0, %1}, %2;" : "=f"(lo), "=f"(hi) : "l"(src))

// ---------------- alloc + bucketize + weight pre-split (B-fragment order) -------
// Cell c (0..31) of a pass covers float4 position p = (c>>3) + 4*(c&7).
// B index: ((d*2+pass)*8 + ks)*256 + n*4 + t, c = ks*4 + t -> per mma instruction
// the warp reads 32 consecutive uint4 (512B).
__global__ void fpnn_alloc_kernel(const float* __restrict__ Wlin,
                                  const float* __restrict__ Wroot) {
    int n = blockIdx.x * blockDim.x + threadIdx.x;
    if (n < N_NODES) {
        int deg = fpnn_deg[n];
        fpnn_off[n] = atomicAdd(&fpnn_cnt[5], deg);
        fpnn_fill[n] = 0;
        int d = min(deg, MAX_DEG);
        int pos = atomicAdd(&fpnn_cnt[d], 1);
        fpnn_lists[d * N_NODES + pos] = n;
    }
    if (n < 20480) {
        int t  = n & 3;
        int ch = (n >> 2) & 63;
        int ks = (n >> 8) & 7;
        int dp = n >> 11;                 // 0..9
        int d = dp >> 1, pass = dp & 1;
        int c = ks * 4 + t;
        int p = (c >> 3) + 4 * (c & 7);   // float4 position 0..31
        const float* w = (pass == 0 ? Wlin : Wroot) + (size_t)d * IN_CH * OUT_CH;
        int k0 = 4 * p;
        float4 f;
        f.x = w[(size_t)k0 * OUT_CH + ch];
        f.y = w[(size_t)(k0 + 1) * OUT_CH + ch];
        f.z = w[(size_t)(k0 + 2) * OUT_CH + ch];
        f.w = w[(size_t)(k0 + 3) * OUT_CH + ch];
        fpnn_wspB[n] = fpnn_split4(f);
    }
}

// ---------------- fill CSR ----------------
__global__ void fpnn_fill_kernel(const int* __restrict__ ei32) {
    int e = blockIdx.x * blockDim.x + threadIdx.x;
    if (e >= N_EDGES) return;
    int st = fpnn_stride;
    int src = ei32[(size_t)st * e];
    int dst = ei32[(size_t)st * (N_EDGES + e)];
    int pos = fpnn_off[dst] + atomicAdd(&fpnn_fill[dst], 1);
    fpnn_csr[pos] = src;
}

#define FPNN_MMA(d, a0, a1, a2, a3, b0, b1)                                   \
    asm volatile(                                                             \
        "mma.sync.aligned.m16n8k16.row.col.f32.bf16.bf16.f32 "                \
        "{%0,%1,%2,%3},{%4,%5,%6,%7},{%8,%9},{%0,%1,%2,%3};"                  \
        : "+f"(d[0]), "+f"(d[1]), "+f"(d[2]), "+f"(d[3])                      \
        : "r"(a0), "r"(a1), "r"(a2), "r"(a3), "r"(b0), "r"(b1))

// ---------------- fused gather + split-bf16 tensor GEMM ----------------
// pass 0 = gathered agg @ Wlin (one CSR walk, f32x2 packed accumulate),
// pass 1 = own x @ Wroot. A via 32KB smem; B direct LDG (L1-hit).
#define M_TILE 64
#define MAX_TILES ((N_NODES + M_TILE - 1) / M_TILE + MAX_DEG + 1)   // 3130
__global__ void __launch_bounds__(256, 3)
fpnn_mma_kernel(const float4* __restrict__ x4) {
    __shared__ uint4 A_s[64 * 32];   // [node][cell 0..31], 32 KB

    int tg = blockIdx.x;
    int d = 0, tile = 0, count = 0;
    {
        int base = 0;
        bool found = false;
#pragma unroll
        for (int b = 0; b <= MAX_DEG; b++) {
            int c = fpnn_cnt[b];
            int t = (c + M_TILE - 1) >> 6;
            if (!found && tg < base + t) {
                d = b; tile = tg - base; count = c; found = true;
            }
            base += t;
        }
        if (!found) return;
    }

    const int* list = fpnn_lists + d * N_NODES;

    int tid = threadIdx.x;
    int nl = tid >> 2, kt = tid & 3;          // A loader: node slot x lane-quarter
    int wid = tid >> 5, lane = tid & 31;
    int m0 = (wid & 3) * 16, n0 = (wid >> 2) * 32;
    int g = lane >> 2, t = lane & 3;

    float acc[4][4];
#pragma unroll
    for (int i = 0; i < 4; i++)
#pragma unroll
        for (int j = 0; j < 4; j++) acc[i][j] = 0.f;

    int nidx = tile * M_TILE + nl;
    int nnode = (nidx < count) ? list[nidx] : -1;

#pragma unroll
    for (int pass = 0; pass < 2; pass++) {
        // ---- A: full 128-float row (8 float4s, positions kt + 4q) ----
        if (pass == 0) {
            unsigned long long vp[16];   // 8 float4 = 16 packed f32x2
#pragma unroll
            for (int q = 0; q < 16; q++) vp[q] = 0ull;
            if (nnode >= 0) {
                int deg = fpnn_deg[nnode];
                int off = fpnn_off[nnode];
                for (int i = 0; i < deg; i++) {
                    int src = fpnn_csr[off + i];
                    const float4* r = x4 + (size_t)src * 32 + kt;
#pragma unroll
                    for (int q = 0; q < 8; q++) {
                        float4 a = r[4 * q];
                        unsigned long long p01, p23;
                        FPNN_PACK64(p01, a.x, a.y);
                        FPNN_PACK64(p23, a.z, a.w);
                        FPNN_ADD2(vp[2 * q],     p01);
                        FPNN_ADD2(vp[2 * q + 1], p23);
                    }
                }
            }
#pragma unroll
            for (int q = 0; q < 8; q++) {
                float4 v;
                FPNN_UNPACK64(v.x, v.y, vp[2 * q]);
                FPNN_UNPACK64(v.z, v.w, vp[2 * q + 1]);
                A_s[nl * 32 + ((kt * 8 + q) ^ (nl & 7))] = fpnn_split4(v);
            }
        } else {
            if (nnode >= 0) {
                const float4* r = x4 + (size_t)nnode * 32 + kt;
#pragma unroll
                for (int q = 0; q < 8; q++)
                    A_s[nl * 32 + ((kt * 8 + q) ^ (nl & 7))] = fpnn_split4(r[4 * q]);
            } else {
                uint4 z; z.x = z.y = z.z = z.w = 0u;
#pragma unroll
                for (int q = 0; q < 8; q++)
                    A_s[nl * 32 + ((kt * 8 + q) ^ (nl & 7))] = z;
            }
        }
        __syncthreads();

        // ---- mma: 8 k-steps of 16; B straight from global (L1-hit, 512B/warp) --
        const uint4* wb = fpnn_wspB + (size_t)((d * 2 + pass) * 8) * 256;
#pragma unroll
        for (int ks = 0; ks < 8; ks++) {
            int c = ks * 4 + t;
            uint4 qa0 = A_s[(m0 + g) * 32 + (c ^ g)];
            uint4 qa1 = A_s[(m0 + g + 8) * 32 + (c ^ g)];
            const uint4* wrow = wb + ks * 256;
#pragma unroll
            for (int ns = 0; ns < 4; ns++) {
                uint4 qb = wrow[(n0 + ns * 8 + g) * 4 + t];
                FPNN_MMA(acc[ns], qa0.x, qa1.x, qa0.z, qa1.z, qb.x, qb.z); // hi*hi
                FPNN_MMA(acc[ns], qa0.x, qa1.x, qa0.z, qa1.z, qb.y, qb.w); // hi*lo
                FPNN_MMA(acc[ns], qa0.y, qa1.y, qa0.w, qa1.w, qb.x, qb.z); // lo*hi
            }
        }
        if (pass == 0) __syncthreads();
    }

    // ---- store ----
    int r0 = tile * M_TILE + m0 + g;
    int r1 = r0 + 8;
#pragma unroll
    for (int ns = 0; ns < 4; ns++) {
        int ncol_half = (n0 >> 1) + ns * 4 + t;
        if (r0 < count) {
            int n = list[r0];
            fpnn_pre2[(size_t)n * 32 + ncol_half] = make_float2(acc[ns][0], acc[ns][1]);
        }
        if (r1 < count) {
            int n = list[r1];
            fpnn_pre2[(size_t)n * 32 + ncol_half] = make_float2(acc[ns][2], acc[ns][3]);
        }
    }
}

// ---------------- fused relu + softmax + pool (warp per 8 sorted nodes) ---------
#define NODES_PER_WARP 8
__global__ void fpnn_spool_kernel(const int* __restrict__ b32,
                                  float* __restrict__ out) {
    int warp = (blockIdx.x * blockDim.x + threadIdx.x) >> 5;
    int lane = threadIdx.x & 31;
    int n0 = warp * NODES_PER_WARP;
    if (n0 >= N_NODES) return;
    int st = fpnn_stride;

    float2 acc = make_float2(0.f, 0.f);
    int gcur = b32[(size_t)st * n0];

#pragma unroll
    for (int i = 0; i < NODES_PER_WARP; i++) {
        int n = n0 + i;
        int g = b32[(size_t)st * n];
        if (g != gcur) {
            atomicAdd(out + (size_t)gcur * OUT_CH + 2 * lane,     acc.x);
            atomicAdd(out + (size_t)gcur * OUT_CH + 2 * lane + 1, acc.y);
            acc = make_float2(0.f, 0.f);
            gcur = g;
        }
        float2 v = fpnn_pre2[(size_t)n * 32 + lane];
        v.x = fmaxf(v.x, 0.f);
        v.y = fmaxf(v.y, 0.f);
        float m = fmaxf(v.x, v.y);
#pragma unroll
        for (int s = 16; s; s >>= 1) m = fmaxf(m, __shfl_xor_sync(0xffffffffu, m, s));
        float ex = __expf(v.x - m), ey = __expf(v.y - m);
        float s = ex + ey;
#pragma unroll
        for (int ss = 16; ss; ss >>= 1) s += __shfl_xor_sync(0xffffffffu, s, ss);
        float inv = 1.0f / s;
        acc.x += ex * inv;
        acc.y += ey * inv;
    }
    atomicAdd(out + (size_t)gcur * OUT_CH + 2 * lane,     acc.x);
    atomicAdd(out + (size_t)gcur * OUT_CH + 2 * lane + 1, acc.y);
}

// ---------------- launch ----------------
extern "C" void kernel_launch(void* const* d_in, const int* in_sizes, int n_in,
                              void* d_out, int out_size) {
    const float* x = 0; const int* ei32 = 0; const int* b32 = 0;
    const float* Wlin = 0; const float* Wroot = 0;
    for (int i = 0; i < n_in; i++) {
        int s = in_sizes[i];
        if      (s == N_NODES * IN_CH)        x    = (const float*)d_in[i];
        else if (s == 2 * N_EDGES)            ei32 = (const int*)d_in[i];
        else if (s == N_NODES)                b32  = (const int*)d_in[i];
        else if (s == (MAX_DEG + 1) * IN_CH * OUT_CH) {
            if (!Wlin) Wlin = (const float*)d_in[i];
            else       Wroot = (const float*)d_in[i];
        }
    }
    if (!x)     x     = (const float*)d_in[0];
    if (!ei32)  ei32  = (const int*)d_in[1];
    if (!b32)   b32   = (const int*)d_in[2];
    if (!Wlin)  Wlin  = (const float*)d_in[3];
    if (!Wroot) Wroot = (const float*)d_in[4];
    float* out = (float*)d_out;

    void* p_deg = 0; void* p_cnt = 0;
    cudaGetSymbolAddress(&p_deg, fpnn_deg);
    cudaGetSymbolAddress(&p_cnt, fpnn_cnt);
    cudaMemsetAsync(p_deg, 0, N_NODES * sizeof(int));
    cudaMemsetAsync(p_cnt, 0, 8 * sizeof(int));
    cudaMemsetAsync(d_out, 0, (size_t)out_size * sizeof(float));

    fpnn_deg_kernel<<<(N_EDGES + 255) / 256, 256>>>(ei32);
    fpnn_alloc_kernel<<<(N_NODES + 255) / 256, 256>>>(Wlin, Wroot);
    fpnn_fill_kernel<<<(N_EDGES + 255) / 256, 256>>>(ei32);
    fpnn_mma_kernel<<<MAX_TILES, 256>>>((const float4*)x);
    fpnn_spool_kernel<<<(N_NODES / NODES_PER_WARP * 32 + 255) / 256, 256>>>(b32, out);
}

// round 17
// speedup vs baseline: 1.3260x; 1.0351x over previous
#include <cuda_runtime.h>
#include <cuda_bf16.h>
#include <cstdint>

#define N_NODES  200000
#define N_EDGES  800000
#define IN_CH    128
#define OUT_CH   64
#define MAX_DEG  4
#define N_GRAPHS 8192

// ---------------- scratch ----------------
__device__ int    fpnn_stride;                        // 1 = int32 inputs, 2 = int64
__device__ int    fpnn_deg[N_NODES];
__device__ int    fpnn_off[N_NODES];
__device__ int    fpnn_fill[N_NODES];
__device__ int    fpnn_csr[N_EDGES];
__device__ int    fpnn_cnt[8];                        // [0..4] buckets, [5] cursor
__device__ int    fpnn_lists[(MAX_DEG + 1) * N_NODES];
// B fragments, warp-contiguous: [((d*2+pass)*8 + ks)*256 + n*4 + t]
__device__ uint4  fpnn_wspB[20480];                   // 320 KB

// ---------------- degree count (+ block-local dtype detect) ----------------
__global__ void fpnn_deg_kernel(const int* __restrict__ ei32) {
    __shared__ int s_st;
    if (threadIdx.x == 0) {
        int nz = 0;
#pragma unroll
        for (int j = 0; j < 8; j++) nz |= ei32[2 * j + 1];
        int st = (nz == 0) ? 2 : 1;
        s_st = st;
        if (blockIdx.x == 0) fpnn_stride = st;
    }
    __syncthreads();
    int e = blockIdx.x * blockDim.x + threadIdx.x;
    if (e >= N_EDGES) return;
    int dst = ei32[(size_t)s_st * (N_EDGES + e)];
    atomicAdd(&fpnn_deg[dst], 1);
}

// ---------------- packed helpers (sm_103a) ----------------
__device__ __forceinline__ unsigned fpnn_cvtpack(float f0, float f1) {
    unsigned r;
    asm("cvt.rn.bf16x2.f32 %0, %1, %2;" : "=r"(r) : "f"(f1), "f"(f0));
    return r;
}
__device__ __forceinline__ uint4 fpnn_split4(float4 v) {
    uint4 q;
    q.x = fpnn_cvtpack(v.x, v.y);
    q.z = fpnn_cvtpack(v.z, v.w);
    float h0 = __uint_as_float(q.x << 16);
    float h1 = __uint_as_float(q.x & 0xffff0000u);
    float h2 = __uint_as_float(q.z << 16);
    float h3 = __uint_as_float(q.z & 0xffff0000u);
    q.y = fpnn_cvtpack(v.x - h0, v.y - h1);
    q.w = fpnn_cvtpack(v.z - h2, v.w - h3);
    return q;
}
#define FPNN_ADD2(acc, val) \
    asm("add.rn.f32x2 %0, %0, %1;" : "+l"(acc) : "l"(val))
#define FPNN_PACK64(dst, lo, hi) \
    asm("mov.b64 %0, {%1, %2};" : "=l"(dst) : "f"(lo), "f"(hi))
#define FPNN_UNPACK64(lo, hi, src) \
    asm("mov.b64 {%0, %1}, %2;" : "=f"(lo), "=f"(hi) : "l"(src))

// ---------------- alloc + bucketize + weight pre-split (B-fragment order) -------
__global__ void fpnn_alloc_kernel(const float* __restrict__ Wlin,
                                  const float* __restrict__ Wroot) {
    int n = blockIdx.x * blockDim.x + threadIdx.x;
    if (n < N_NODES) {
        int deg = fpnn_deg[n];
        fpnn_off[n] = atomicAdd(&fpnn_cnt[5], deg);
        fpnn_fill[n] = 0;
        int d = min(deg, MAX_DEG);
        int pos = atomicAdd(&fpnn_cnt[d], 1);
        fpnn_lists[d * N_NODES + pos] = n;
    }
    if (n < 20480) {
        int t  = n & 3;
        int ch = (n >> 2) & 63;
        int ks = (n >> 8) & 7;
        int dp = n >> 11;                 // 0..9
        int d = dp >> 1, pass = dp & 1;
        int c = ks * 4 + t;
        int p = (c >> 3) + 4 * (c & 7);   // float4 position 0..31
        const float* w = (pass == 0 ? Wlin : Wroot) + (size_t)d * IN_CH * OUT_CH;
        int k0 = 4 * p;
        float4 f;
        f.x = w[(size_t)k0 * OUT_CH + ch];
        f.y = w[(size_t)(k0 + 1) * OUT_CH + ch];
        f.z = w[(size_t)(k0 + 2) * OUT_CH + ch];
        f.w = w[(size_t)(k0 + 3) * OUT_CH + ch];
        fpnn_wspB[n] = fpnn_split4(f);
    }
}

// ---------------- fill CSR ----------------
__global__ void fpnn_fill_kernel(const int* __restrict__ ei32) {
    int e = blockIdx.x * blockDim.x + threadIdx.x;
    if (e >= N_EDGES) return;
    int st = fpnn_stride;
    int src = ei32[(size_t)st * e];
    int dst = ei32[(size_t)st * (N_EDGES + e)];
    int pos = fpnn_off[dst] + atomicAdd(&fpnn_fill[dst], 1);
    fpnn_csr[pos] = src;
}

#define FPNN_MMA(d, a0, a1, a2, a3, b0, b1)                                   \
    asm volatile(                                                             \
        "mma.sync.aligned.m16n8k16.row.col.f32.bf16.bf16.f32 "                \
        "{%0,%1,%2,%3},{%4,%5,%6,%7},{%8,%9},{%0,%1,%2,%3};"                  \
        : "+f"(d[0]), "+f"(d[1]), "+f"(d[2]), "+f"(d[3])                      \
        : "r"(a0), "r"(a1), "r"(a2), "r"(a3), "r"(b0), "r"(b1))

// ---------------- fused gather + GEMM + relu + softmax + pool -------------------
// pass 0 = gathered agg @ Wlin (one CSR walk), pass 1 = own x @ Wroot.
// Epilogue: block-local row softmax (rows live entirely in this block) and
// atomicAdd pooling straight into out. No intermediate node-feature buffer.
#define M_TILE 64
#define MAX_TILES ((N_NODES + M_TILE - 1) / M_TILE + MAX_DEG + 1)   // 3130
__global__ void __launch_bounds__(256, 3)
fpnn_mma_kernel(const float4* __restrict__ x4,
                const int* __restrict__ b32,
                float* __restrict__ out) {
    __shared__ uint4 A_s[64 * 32];   // [node][cell 0..31], 32 KB (reused by epi)

    int tg = blockIdx.x;
    int d = 0, tile = 0, count = 0;
    {
        int base = 0;
        bool found = false;
#pragma unroll
        for (int b = 0; b <= MAX_DEG; b++) {
            int c = fpnn_cnt[b];
            int t = (c + M_TILE - 1) >> 6;
            if (!found && tg < base + t) {
                d = b; tile = tg - base; count = c; found = true;
            }
            base += t;
        }
        if (!found) return;
    }

    const int* list = fpnn_lists + d * N_NODES;

    int tid = threadIdx.x;
    int nl = tid >> 2, kt = tid & 3;          // A loader: node slot x lane-quarter
    int wid = tid >> 5, lane = tid & 31;
    int m0 = (wid & 3) * 16, n0 = (wid >> 2) * 32;
    int half = wid >> 2;                      // which 32-channel half
    int g = lane >> 2, t = lane & 3;

    float acc[4][4];
#pragma unroll
    for (int i = 0; i < 4; i++)
#pragma unroll
        for (int j = 0; j < 4; j++) acc[i][j] = 0.f;

    int nidx = tile * M_TILE + nl;
    int nnode = (nidx < count) ? list[nidx] : -1;

#pragma unroll
    for (int pass = 0; pass < 2; pass++) {
        if (pass == 0) {
            unsigned long long vp[16];   // 8 float4 = 16 packed f32x2
#pragma unroll
            for (int q = 0; q < 16; q++) vp[q] = 0ull;
            if (nnode >= 0) {
                int deg = fpnn_deg[nnode];
                int off = fpnn_off[nnode];
                for (int i = 0; i < deg; i++) {
                    int src = fpnn_csr[off + i];
                    const float4* r = x4 + (size_t)src * 32 + kt;
#pragma unroll
                    for (int q = 0; q < 8; q++) {
                        float4 a = r[4 * q];
                        unsigned long long p01, p23;
                        FPNN_PACK64(p01, a.x, a.y);
                        FPNN_PACK64(p23, a.z, a.w);
                        FPNN_ADD2(vp[2 * q],     p01);
                        FPNN_ADD2(vp[2 * q + 1], p23);
                    }
                }
            }
#pragma unroll
            for (int q = 0; q < 8; q++) {
                float4 v;
                FPNN_UNPACK64(v.x, v.y, vp[2 * q]);
                FPNN_UNPACK64(v.z, v.w, vp[2 * q + 1]);
                A_s[nl * 32 + ((kt * 8 + q) ^ (nl & 7))] = fpnn_split4(v);
            }
        } else {
            if (nnode >= 0) {
                const float4* r = x4 + (size_t)nnode * 32 + kt;
#pragma unroll
                for (int q = 0; q < 8; q++)
                    A_s[nl * 32 + ((kt * 8 + q) ^ (nl & 7))] = fpnn_split4(r[4 * q]);
            } else {
                uint4 z; z.x = z.y = z.z = z.w = 0u;
#pragma unroll
                for (int q = 0; q < 8; q++)
                    A_s[nl * 32 + ((kt * 8 + q) ^ (nl & 7))] = z;
            }
        }
        __syncthreads();

        const uint4* wb = fpnn_wspB + (size_t)((d * 2 + pass) * 8) * 256;
#pragma unroll
        for (int ks = 0; ks < 8; ks++) {
            int c = ks * 4 + t;
            uint4 qa0 = A_s[(m0 + g) * 32 + (c ^ g)];
            uint4 qa1 = A_s[(m0 + g + 8) * 32 + (c ^ g)];
            const uint4* wrow = wb + ks * 256;
#pragma unroll
            for (int ns = 0; ns < 4; ns++) {
                uint4 qb = wrow[(n0 + ns * 8 + g) * 4 + t];
                FPNN_MMA(acc[ns], qa0.x, qa1.x, qa0.z, qa1.z, qb.x, qb.z); // hi*hi
                FPNN_MMA(acc[ns], qa0.x, qa1.x, qa0.z, qa1.z, qb.y, qb.w); // hi*lo
                FPNN_MMA(acc[ns], qa0.y, qa1.y, qa0.w, qa1.w, qb.x, qb.z); // lo*hi
            }
        }
        __syncthreads();   // A_s reusable (also protects pass-1 overwrite)
    }

    // ================= fused epilogue: relu + softmax + pool =================
    // Thread holds rows ra = m0+g, rb = ra+8 (tile-local), channels
    // 2*(half*16 + ns*4 + t) and +1, ns = 0..3.
    float* red = (float*)A_s;    // reduction scratch: [row(64)][half(2)] x2 rounds

    // relu in place
#pragma unroll
    for (int ns = 0; ns < 4; ns++)
#pragma unroll
        for (int j = 0; j < 4; j++) acc[ns][j] = fmaxf(acc[ns][j], 0.f);

    // per-thread max over 8 channels per row
    float mxa = 0.f, mxb = 0.f;
#pragma unroll
    for (int ns = 0; ns < 4; ns++) {
        mxa = fmaxf(mxa, fmaxf(acc[ns][0], acc[ns][1]));
        mxb = fmaxf(mxb, fmaxf(acc[ns][2], acc[ns][3]));
    }
    // reduce over t-quad (lanes g*4+t)
#pragma unroll
    for (int s = 1; s <= 2; s <<= 1) {
        mxa = fmaxf(mxa, __shfl_xor_sync(0xffffffffu, mxa, s));
        mxb = fmaxf(mxb, __shfl_xor_sync(0xffffffffu, mxb, s));
    }
    // cross-half combine via smem
    if (t == 0) {
        red[(m0 + g) * 2 + half]     = mxa;
        red[(m0 + g + 8) * 2 + half] = mxb;
    }
    __syncthreads();
    mxa = fmaxf(red[(m0 + g) * 2],     red[(m0 + g) * 2 + 1]);
    mxb = fmaxf(red[(m0 + g + 8) * 2], red[(m0 + g + 8) * 2 + 1]);

    // exp + per-thread sums
    float sa = 0.f, sb = 0.f;
#pragma unroll
    for (int ns = 0; ns < 4; ns++) {
        acc[ns][0] = __expf(acc[ns][0] - mxa);
        acc[ns][1] = __expf(acc[ns][1] - mxa);
        acc[ns][2] = __expf(acc[ns][2] - mxb);
        acc[ns][3] = __expf(acc[ns][3] - mxb);
        sa += acc[ns][0] + acc[ns][1];
        sb += acc[ns][2] + acc[ns][3];
    }
#pragma unroll
    for (int s = 1; s <= 2; s <<= 1) {
        sa += __shfl_xor_sync(0xffffffffu, sa, s);
        sb += __shfl_xor_sync(0xffffffffu, sb, s);
    }
    if (t == 0) {
        red[128 + (m0 + g) * 2 + half]     = sa;
        red[128 + (m0 + g + 8) * 2 + half] = sb;
    }
    __syncthreads();
    float inva = 1.0f / (red[128 + (m0 + g) * 2]     + red[128 + (m0 + g) * 2 + 1]);
    float invb = 1.0f / (red[128 + (m0 + g + 8) * 2] + red[128 + (m0 + g + 8) * 2 + 1]);

    // pool: atomicAdd normalized values into out[graph]
    int st = fpnn_stride;
    int ra = tile * M_TILE + m0 + g;
    int rb = ra + 8;
    if (ra < count) {
        int node = list[ra];
        int gr = b32[(size_t)st * node];
        float* dst = out + (size_t)gr * OUT_CH + (half * 16 + t) * 2;
#pragma unroll
        for (int ns = 0; ns < 4; ns++) {
            atomicAdd(dst + ns * 8,     acc[ns][0] * inva);
            atomicAdd(dst + ns * 8 + 1, acc[ns][1] * inva);
        }
    }
    if (rb < count) {
        int node = list[rb];
        int gr = b32[(size_t)st * node];
        float* dst = out + (size_t)gr * OUT_CH + (half * 16 + t) * 2;
#pragma unroll
        for (int ns = 0; ns < 4; ns++) {
            atomicAdd(dst + ns * 8,     acc[ns][2] * invb);
            atomicAdd(dst + ns * 8 + 1, acc[ns][3] * invb);
        }
    }
}

// ---------------- launch ----------------
extern "C" void kernel_launch(void* const* d_in, const int* in_sizes, int n_in,
                              void* d_out, int out_size) {
    const float* x = 0; const int* ei32 = 0; const int* b32 = 0;
    const float* Wlin = 0; const float* Wroot = 0;
    for (int i = 0; i < n_in; i++) {
        int s = in_sizes[i];
        if      (s == N_NODES * IN_CH)        x    = (const float*)d_in[i];
        else if (s == 2 * N_EDGES)            ei32 = (const int*)d_in[i];
        else if (s == N_NODES)                b32  = (const int*)d_in[i];
        else if (s == (MAX_DEG + 1) * IN_CH * OUT_CH) {
            if (!Wlin) Wlin = (const float*)d_in[i];
            else       Wroot = (const float*)d_in[i];
        }
    }
    if (!x)     x     = (const float*)d_in[0];
    if (!ei32)  ei32  = (const int*)d_in[1];
    if (!b32)   b32   = (const int*)d_in[2];
    if (!Wlin)  Wlin  = (const float*)d_in[3];
    if (!Wroot) Wroot = (const float*)d_in[4];
    float* out = (float*)d_out;

    void* p_deg = 0; void* p_cnt = 0;
    cudaGetSymbolAddress(&p_deg, fpnn_deg);
    cudaGetSymbolAddress(&p_cnt, fpnn_cnt);
    cudaMemsetAsync(p_deg, 0, N_NODES * sizeof(int));
    cudaMemsetAsync(p_cnt, 0, 8 * sizeof(int));
    cudaMemsetAsync(d_out, 0, (size_t)out_size * sizeof(float));

    fpnn_deg_kernel<<<(N_EDGES + 255) / 256, 256>>>(ei32);
    fpnn_alloc_kernel<<<(N_NODES + 255) / 256, 256>>>(Wlin, Wroot);
    fpnn_fill_kernel<<<(N_EDGES + 255) / 256, 256>>>(ei32);
    fpnn_mma_kernel<<<MAX_TILES, 256>>>((const float4*)x, b32, out);
}